// round 1
// baseline (speedup 1.0000x reference)
#include <cuda_runtime.h>
#include <cuda_bf16.h>
#include <math.h>

// Problem constants
#define Bsz 8
#define H   12
#define Nq  1024
#define Dh  64
#define SCALE 0.125f
#define EPS 1e-6f

#define BM 64
#define BN 64
#define NTHREADS 256
#define LDS 68   // row stride in floats (64 + 4 pad, keeps 16B alignment)

// Shared layout (floats):
//   Qt  [64][LDS]  : Qt[d][m]   (d-major, transposed)
//   Kt  [64][LDS]  : Kt[d][n]
//   Vs  [64][LDS]  : Vs[n][d]
//   Ss  [64][LDS]  : Ss[n][m]   (attn tile, n-major for the O-GEMM)
//   rsum[64], psum[4*64]
#define SMEM_FLOATS (4 * 64 * LDS + 64 + 4 * 64)

__global__ __launch_bounds__(NTHREADS) void l2q_attn_kernel(
    const float* __restrict__ q, const float* __restrict__ k,
    const float* __restrict__ v, const float* __restrict__ alpha,
    const float* __restrict__ beta, const float* __restrict__ gamma,
    float* __restrict__ out)
{
    extern __shared__ float sm[];
    float* Qt   = sm;
    float* Kt   = Qt + 64 * LDS;
    float* Vs   = Kt + 64 * LDS;
    float* Ss   = Vs + 64 * LDS;
    float* rsum = Ss + 64 * LDS;
    float* psum = rsum + 64;

    const int bh = blockIdx.y;           // 0..B*H-1
    const int h  = bh % H;
    const int m0 = blockIdx.x * BM;

    const float* qb = q + (size_t)bh * Nq * Dh;
    const float* kb = k + (size_t)bh * Nq * Dh;
    const float* vb = v + (size_t)bh * Nq * Dh;
    float*       ob = out + (size_t)bh * Nq * Dh;

    const float a2 = alpha[h] * SCALE * SCALE;
    const float b1 = beta[h] * SCALE;
    const float g0 = gamma[h];

    const int tid = threadIdx.x;
    const int tx = tid & 15;   // 16 cols of threads -> n (S) / d (O)
    const int ty = tid >> 4;   // 16 rows of threads -> m

    // Load Q tile transposed: Qt[d][m]
    #pragma unroll
    for (int i = tid; i < BM * Dh; i += NTHREADS) {
        int m = i >> 6, d = i & 63;
        Qt[d * LDS + m] = qb[(size_t)(m0 + m) * Dh + d];
    }
    if (tid < 64) rsum[tid] = 0.f;

    float o[4][4];
    #pragma unroll
    for (int i = 0; i < 4; i++)
        #pragma unroll
        for (int j = 0; j < 4; j++) o[i][j] = 0.f;

    __syncthreads();

    for (int n0 = 0; n0 < Nq; n0 += BN) {
        // Load K (transposed, d-major) and V (natural) tiles
        #pragma unroll
        for (int i = tid; i < BN * Dh; i += NTHREADS) {
            int n = i >> 6, d = i & 63;
            float kv = kb[(size_t)(n0 + n) * Dh + d];
            float vv = vb[(size_t)(n0 + n) * Dh + d];
            Kt[d * LDS + n] = kv;
            Vs[n * LDS + d] = vv;
        }
        __syncthreads();

        // ---- S = Q K^T (raw dot products) ----
        float s[4][4];
        #pragma unroll
        for (int i = 0; i < 4; i++)
            #pragma unroll
            for (int j = 0; j < 4; j++) s[i][j] = 0.f;

        #pragma unroll 8
        for (int kk = 0; kk < Dh; kk++) {
            float4 a = *(const float4*)&Qt[kk * LDS + ty * 4];
            float4 b = *(const float4*)&Kt[kk * LDS + tx * 4];
            const float av[4] = {a.x, a.y, a.z, a.w};
            const float bv[4] = {b.x, b.y, b.z, b.w};
            #pragma unroll
            for (int i = 0; i < 4; i++)
                #pragma unroll
                for (int j = 0; j < 4; j++)
                    s[i][j] = fmaf(av[i], bv[j], s[i][j]);
        }

        // ---- attn = relu(a2*s^2 + b1*s + g0), store transposed Ss[n][m] ----
        #pragma unroll
        for (int i = 0; i < 4; i++) {
            #pragma unroll
            for (int j = 0; j < 4; j++) {
                float sv = s[i][j];
                float p = fmaf(fmaf(a2, sv, b1), sv, g0);
                p = fmaxf(p, 0.f);
                Ss[(tx * 4 + j) * LDS + (ty * 4 + i)] = p;
            }
        }
        __syncthreads();

        // ---- row sums of attn tile (reduce over n) ----
        {
            int row = tid & 63, q4 = tid >> 6;
            float ps = 0.f;
            #pragma unroll
            for (int n = 0; n < 16; n++)
                ps += Ss[(q4 * 16 + n) * LDS + row];
            psum[q4 * 64 + row] = ps;
        }
        __syncthreads();
        if (tid < 64)
            rsum[tid] += psum[tid] + psum[64 + tid] + psum[128 + tid] + psum[192 + tid];

        // ---- O += attn @ V ----
        #pragma unroll 8
        for (int n = 0; n < BN; n++) {
            float4 a = *(const float4*)&Ss[n * LDS + ty * 4];
            float4 b = *(const float4*)&Vs[n * LDS + tx * 4];
            const float av[4] = {a.x, a.y, a.z, a.w};
            const float bv[4] = {b.x, b.y, b.z, b.w};
            #pragma unroll
            for (int i = 0; i < 4; i++)
                #pragma unroll
                for (int j = 0; j < 4; j++)
                    o[i][j] = fmaf(av[i], bv[j], o[i][j]);
        }
        __syncthreads();  // protect Kt/Vs/Ss/psum before next-iteration overwrite
    }

    __syncthreads();  // all rsum updates visible

    #pragma unroll
    for (int i = 0; i < 4; i++) {
        float r = 1.f / (rsum[ty * 4 + i] + EPS);
        float4 val;
        val.x = o[i][0] * r;
        val.y = o[i][1] * r;
        val.z = o[i][2] * r;
        val.w = o[i][3] * r;
        *(float4*)&ob[(size_t)(m0 + ty * 4 + i) * Dh + tx * 4] = val;
    }
}

extern "C" void kernel_launch(void* const* d_in, const int* in_sizes, int n_in,
                              void* d_out, int out_size)
{
    const float* q     = (const float*)d_in[0];
    const float* k     = (const float*)d_in[1];
    const float* v     = (const float*)d_in[2];
    const float* alpha = (const float*)d_in[3];
    const float* beta  = (const float*)d_in[4];
    const float* gamma = (const float*)d_in[5];
    float* out = (float*)d_out;

    static_assert(SMEM_FLOATS * sizeof(float) < 228 * 1024, "smem");
    const int smem_bytes = SMEM_FLOATS * sizeof(float);
    cudaFuncSetAttribute(l2q_attn_kernel,
                         cudaFuncAttributeMaxDynamicSharedMemorySize, smem_bytes);

    dim3 grid(Nq / BM, Bsz * H);
    l2q_attn_kernel<<<grid, NTHREADS, smem_bytes>>>(q, k, v, alpha, beta, gamma, out);
}

// round 2
// speedup vs baseline: 2.6328x; 2.6328x over previous
#include <cuda_runtime.h>
#include <stdint.h>

#define Bsz 8
#define H   12
#define Nq  1024
#define Dh  64
#define SCALE 0.125f
#define EPS 1e-6f

#define BM 128
#define BN 64
#define NTHREADS 256

// smem strides (32-bit words), padded for conflict-free fragment access
#define QS 68   // Qs[m][k]
#define KS 72   // Kt[k][n]  (K transposed)
#define VS 72   // Vs[k][d]  (V natural: k = key index)
#define SS 68   // Ss[m][n]  (attn tile, tf32-rounded)

// word offsets
#define OFF_Q  0
#define OFF_K  (OFF_Q + 128 * QS)          // 8704
#define OFF_V  (OFF_K + 64 * KS)           // 13312
#define OFF_S  (OFF_V + 64 * VS)           // 17920
#define OFF_R  (OFF_S + 128 * SS)          // 26624
#define SMEM_WORDS (OFF_R + 2 * 128)       // 26880 words = 107520 B

__device__ __forceinline__ uint32_t f2tf(float x) {
    uint32_t u;
    asm("cvt.rna.tf32.f32 %0, %1;" : "=r"(u) : "f"(x));
    return u;
}

__device__ __forceinline__ void mma8(float c[4],
                                     uint32_t a0, uint32_t a1, uint32_t a2, uint32_t a3,
                                     uint32_t b0, uint32_t b1) {
    asm volatile(
        "mma.sync.aligned.m16n8k8.row.col.f32.tf32.tf32.f32 "
        "{%0,%1,%2,%3},{%4,%5,%6,%7},{%8,%9},{%0,%1,%2,%3};\n"
        : "+f"(c[0]), "+f"(c[1]), "+f"(c[2]), "+f"(c[3])
        : "r"(a0), "r"(a1), "r"(a2), "r"(a3), "r"(b0), "r"(b1));
}

__global__ __launch_bounds__(NTHREADS, 2) void l2q_mma_kernel(
    const float* __restrict__ q, const float* __restrict__ k,
    const float* __restrict__ v, const float* __restrict__ alpha,
    const float* __restrict__ beta, const float* __restrict__ gamma,
    float* __restrict__ out)
{
    extern __shared__ uint32_t sm[];
    uint32_t* Qs = sm + OFF_Q;
    uint32_t* Kt = sm + OFF_K;
    uint32_t* Vs = sm + OFF_V;
    uint32_t* Ss = sm + OFF_S;
    float*  rsum = (float*)(sm + OFF_R);

    const int bh = blockIdx.y;
    const int h  = bh % H;
    const int m0 = blockIdx.x * BM;

    const float* qb = q + (size_t)bh * Nq * Dh;
    const float* kb = k + (size_t)bh * Nq * Dh;
    const float* vb = v + (size_t)bh * Nq * Dh;
    float*       ob = out + (size_t)bh * Nq * Dh;

    const float a2c = alpha[h] * SCALE * SCALE;
    const float b1c = beta[h] * SCALE;
    const float g0c = gamma[h];

    const int tid  = threadIdx.x;
    const int lane = tid & 31;
    const int wid  = tid >> 5;
    const int g    = lane >> 2;   // group id (row within frag)
    const int t    = lane & 3;    // thread-in-group (k/col select)
    const int wm   = wid >> 1;    // 0..3 : m-group of 32 rows
    const int wn   = wid & 1;     // 0..1 : n-group (S) / d-group (O) of 32 cols

    // ---- stage Q (tf32-rounded) ----
    #pragma unroll
    for (int i = tid; i < BM * Dh; i += NTHREADS) {
        int m = i >> 6, d = i & 63;
        Qs[m * QS + d] = f2tf(qb[(size_t)(m0 + m) * Dh + d]);
    }

    float o[2][4][4];
    #pragma unroll
    for (int mf = 0; mf < 2; mf++)
        #pragma unroll
        for (int df = 0; df < 4; df++)
            #pragma unroll
            for (int r = 0; r < 4; r++) o[mf][df][r] = 0.f;

    float rs[2][2] = {{0.f, 0.f}, {0.f, 0.f}};

    for (int n0 = 0; n0 < Nq; n0 += BN) {
        __syncthreads();  // covers Q staging on first iter; Kt/Vs/Ss reuse after
        // ---- stage K (transposed) and V ----
        #pragma unroll
        for (int i = tid; i < BN * Dh; i += NTHREADS) {
            int n = i >> 6, d = i & 63;
            Kt[d * KS + n] = f2tf(kb[(size_t)(n0 + n) * Dh + d]);
            Vs[n * VS + d] = f2tf(vb[(size_t)(n0 + n) * Dh + d]);
        }
        __syncthreads();

        // ---- S = Q K^T via mma.sync tf32 ----
        float c[2][4][4];
        #pragma unroll
        for (int mf = 0; mf < 2; mf++)
            #pragma unroll
            for (int nf = 0; nf < 4; nf++)
                #pragma unroll
                for (int r = 0; r < 4; r++) c[mf][nf][r] = 0.f;

        #pragma unroll
        for (int ks = 0; ks < 8; ks++) {
            uint32_t a[2][4];
            #pragma unroll
            for (int mf = 0; mf < 2; mf++) {
                int base = (wm * 32 + mf * 16 + g) * QS + ks * 8 + t;
                a[mf][0] = Qs[base];
                a[mf][1] = Qs[base + 8 * QS];
                a[mf][2] = Qs[base + 4];
                a[mf][3] = Qs[base + 8 * QS + 4];
            }
            #pragma unroll
            for (int nf = 0; nf < 4; nf++) {
                int col = wn * 32 + nf * 8 + g;
                uint32_t b0 = Kt[(ks * 8 + t) * KS + col];
                uint32_t b1 = Kt[(ks * 8 + t + 4) * KS + col];
                #pragma unroll
                for (int mf = 0; mf < 2; mf++)
                    mma8(c[mf][nf], a[mf][0], a[mf][1], a[mf][2], a[mf][3], b0, b1);
            }
        }

        // ---- poly + relu + rowsum + store attn (tf32) ----
        #pragma unroll
        for (int mf = 0; mf < 2; mf++) {
            int row = wm * 32 + mf * 16 + g;
            #pragma unroll
            for (int nf = 0; nf < 4; nf++) {
                int col = wn * 32 + nf * 8 + 2 * t;
                float p[4];
                #pragma unroll
                for (int r = 0; r < 4; r++) {
                    float s = c[mf][nf][r];
                    float pv = fmaf(fmaf(a2c, s, b1c), s, g0c);
                    pv = fmaxf(pv, 0.f);
                    p[r] = __uint_as_float(f2tf(pv));  // round once, use same value for sum & matmul
                }
                rs[mf][0] += p[0] + p[1];
                rs[mf][1] += p[2] + p[3];
                uint2 lo = {__float_as_uint(p[0]), __float_as_uint(p[1])};
                uint2 hi = {__float_as_uint(p[2]), __float_as_uint(p[3])};
                *(uint2*)&Ss[row * SS + col] = lo;
                *(uint2*)&Ss[(row + 8) * SS + col] = hi;
            }
        }
        __syncthreads();

        // ---- O += attn @ V ----
        #pragma unroll
        for (int ks = 0; ks < 8; ks++) {
            uint32_t a[2][4];
            #pragma unroll
            for (int mf = 0; mf < 2; mf++) {
                int base = (wm * 32 + mf * 16 + g) * SS + ks * 8 + t;
                a[mf][0] = Ss[base];
                a[mf][1] = Ss[base + 8 * SS];
                a[mf][2] = Ss[base + 4];
                a[mf][3] = Ss[base + 8 * SS + 4];
            }
            #pragma unroll
            for (int df = 0; df < 4; df++) {
                int col = wn * 32 + df * 8 + g;
                uint32_t b0 = Vs[(ks * 8 + t) * VS + col];
                uint32_t b1 = Vs[(ks * 8 + t + 4) * VS + col];
                #pragma unroll
                for (int mf = 0; mf < 2; mf++)
                    mma8(o[mf][df], a[mf][0], a[mf][1], a[mf][2], a[mf][3], b0, b1);
            }
        }
    }

    // ---- rowsum: reduce over k-quad lanes, then across the two wn warps ----
    #pragma unroll
    for (int mf = 0; mf < 2; mf++)
        #pragma unroll
        for (int j = 0; j < 2; j++) {
            rs[mf][j] += __shfl_xor_sync(0xFFFFFFFFu, rs[mf][j], 1);
            rs[mf][j] += __shfl_xor_sync(0xFFFFFFFFu, rs[mf][j], 2);
        }
    if (t == 0) {
        #pragma unroll
        for (int mf = 0; mf < 2; mf++) {
            int row = wm * 32 + mf * 16 + g;
            rsum[wn * 128 + row]     = rs[mf][0];
            rsum[wn * 128 + row + 8] = rs[mf][1];
        }
    }
    __syncthreads();

    // ---- normalize + store O ----
    #pragma unroll
    for (int mf = 0; mf < 2; mf++) {
        int row = wm * 32 + mf * 16 + g;
        float r0 = 1.f / (rsum[row]     + rsum[128 + row]     + EPS);
        float r1 = 1.f / (rsum[row + 8] + rsum[128 + row + 8] + EPS);
        #pragma unroll
        for (int df = 0; df < 4; df++) {
            int col = wn * 32 + df * 8 + 2 * t;
            float2 lo = {o[mf][df][0] * r0, o[mf][df][1] * r0};
            float2 hi = {o[mf][df][2] * r1, o[mf][df][3] * r1};
            *(float2*)&ob[(size_t)(m0 + row) * Dh + col]     = lo;
            *(float2*)&ob[(size_t)(m0 + row + 8) * Dh + col] = hi;
        }
    }
}

extern "C" void kernel_launch(void* const* d_in, const int* in_sizes, int n_in,
                              void* d_out, int out_size)
{
    const float* q     = (const float*)d_in[0];
    const float* k     = (const float*)d_in[1];
    const float* v     = (const float*)d_in[2];
    const float* alpha = (const float*)d_in[3];
    const float* beta  = (const float*)d_in[4];
    const float* gamma = (const float*)d_in[5];
    float* out = (float*)d_out;

    const int smem_bytes = SMEM_WORDS * sizeof(uint32_t);
    cudaFuncSetAttribute(l2q_mma_kernel,
                         cudaFuncAttributeMaxDynamicSharedMemorySize, smem_bytes);

    dim3 grid(Nq / BM, Bsz * H);
    l2q_mma_kernel<<<grid, NTHREADS, smem_bytes>>>(q, k, v, alpha, beta, gamma, out);
}

// round 4
// speedup vs baseline: 7.4260x; 2.8205x over previous
#include <cuda_runtime.h>
#include <cuda_fp16.h>
#include <stdint.h>

#define Bsz 8
#define H   12
#define Nq  1024
#define Dh  64
#define SCALE 0.125f
#define EPS 1e-6f

#define BM 128
#define BN 64
#define NT 256
#define NTILES (Nq / BN)   // 16
#define RPITCH 144          // bytes per smem row (72 halves: 64 data + 8 pad)

// smem byte offsets
#define SM_Q  0                       // 128 rows -> 18432 B
#define SM_K0 18432                   // 64 rows  -> 9216 B
#define SM_K1 (18432 + 9216)
#define SM_V0 36864
#define SM_V1 (36864 + 9216)
#define SMEM_BYTES 55296

__device__ __forceinline__ uint32_t s2u(const void* p) {
    uint32_t a;
    asm("{ .reg .u64 t; cvta.to.shared.u64 t, %1; cvt.u32.u64 %0, t; }" : "=r"(a) : "l"(p));
    return a;
}
__device__ __forceinline__ uint32_t ph2(float lo, float hi) {
    __half2 h = __floats2half2_rn(lo, hi);   // .x = lo, .y = hi
    return *(uint32_t*)&h;
}
__device__ __forceinline__ void ldm_x4(uint32_t r[4], uint32_t addr) {
    asm volatile("ldmatrix.sync.aligned.m8n8.x4.shared.b16 {%0,%1,%2,%3}, [%4];"
                 : "=r"(r[0]), "=r"(r[1]), "=r"(r[2]), "=r"(r[3]) : "r"(addr));
}
__device__ __forceinline__ void ldm_x4t(uint32_t r[4], uint32_t addr) {
    asm volatile("ldmatrix.sync.aligned.m8n8.x4.trans.shared.b16 {%0,%1,%2,%3}, [%4];"
                 : "=r"(r[0]), "=r"(r[1]), "=r"(r[2]), "=r"(r[3]) : "r"(addr));
}
__device__ __forceinline__ void mma16(float c[4], const uint32_t a[4],
                                      uint32_t b0, uint32_t b1) {
    asm volatile(
        "mma.sync.aligned.m16n8k16.row.col.f32.f16.f16.f32 "
        "{%0,%1,%2,%3},{%4,%5,%6,%7},{%8,%9},{%0,%1,%2,%3};\n"
        : "+f"(c[0]), "+f"(c[1]), "+f"(c[2]), "+f"(c[3])
        : "r"(a[0]), "r"(a[1]), "r"(a[2]), "r"(a[3]), "r"(b0), "r"(b1));
}

__global__ __launch_bounds__(NT, 2) void l2q_h2_kernel(
    const float* __restrict__ q, const float* __restrict__ k,
    const float* __restrict__ v, const float* __restrict__ alpha,
    const float* __restrict__ beta, const float* __restrict__ gamma,
    float* __restrict__ out)
{
    extern __shared__ char smc[];
    const uint32_t sb = s2u(smc);

    const int tid  = threadIdx.x;
    const int w    = tid >> 5;    // warp 0..7 -> rows w*16..w*16+15
    const int lane = tid & 31;
    const int g    = lane >> 2;
    const int t    = lane & 3;

    const int bh = blockIdx.y;
    const int h  = bh % H;
    const int m0 = blockIdx.x * BM;

    const float* qb = q + (size_t)bh * Nq * Dh;
    const float* kb = k + (size_t)bh * Nq * Dh;
    const float* vb = v + (size_t)bh * Nq * Dh;
    float*       ob = out + (size_t)bh * Nq * Dh;

    const float a2c = alpha[h] * SCALE * SCALE;
    const float b1c = beta[h] * SCALE;
    const float g0c = gamma[h];

    // ---- per-lane ldmatrix address offsets ----
    // A (Q, row-major): lanes 0-15 -> rows (lane&15), lanes 16-31 -> same rows, k+8
    const uint32_t qaddr = sb + SM_Q + (uint32_t)(w * 16 + (lane & 15)) * RPITCH
                         + (uint32_t)((lane >> 4) << 4);
    // B (K natural = col-major k x n): groups (rows p16+l,k0)(rows,k0+8)(rows+8,k0)(rows+8,k0+8)
    const uint32_t krow_off = (uint32_t)((lane & 7) + ((lane >> 4) << 3)) * RPITCH
                            + (uint32_t)(((lane >> 3) & 1) << 4);
    // B (V row-major, .trans): groups (k0,d0)(k0+8,d0)(k0,d0+8)(k0+8,d0+8); rows = keys
    const uint32_t vrow_off = (uint32_t)((lane & 7) + (((lane >> 3) & 1) << 3)) * RPITCH
                            + (uint32_t)((lane >> 4) << 4);

    // ---- staging index: each thread owns column c (float4) of rows rbase+16j ----
    const int rbase = tid >> 4;
    const int cc    = tid & 15;

    // ---- stage Q (fp32 -> fp16, coalesced, conflict-free) ----
    #pragma unroll
    for (int j = 0; j < 8; j++) {
        int row = rbase + 16 * j;
        float4 f = *(const float4*)(qb + (size_t)(m0 + row) * Dh + cc * 4);
        *(uint2*)(smc + SM_Q + row * RPITCH + cc * 8) =
            make_uint2(ph2(f.x, f.y), ph2(f.z, f.w));
    }
    // ---- stage K/V tile 0 into buffer 0 ----
    #pragma unroll
    for (int j = 0; j < 4; j++) {
        int row = rbase + 16 * j;
        float4 fk = *(const float4*)(kb + (size_t)row * Dh + cc * 4);
        float4 fv = *(const float4*)(vb + (size_t)row * Dh + cc * 4);
        *(uint2*)(smc + SM_K0 + row * RPITCH + cc * 8) =
            make_uint2(ph2(fk.x, fk.y), ph2(fk.z, fk.w));
        *(uint2*)(smc + SM_V0 + row * RPITCH + cc * 8) =
            make_uint2(ph2(fv.x, fv.y), ph2(fv.z, fv.w));
    }
    __syncthreads();

    float o[8][4];
    #pragma unroll
    for (int d = 0; d < 8; d++)
        #pragma unroll
        for (int r = 0; r < 4; r++) o[d][r] = 0.f;
    float rs0 = 0.f, rs1 = 0.f;

    for (int tt = 0; tt < NTILES; tt++) {
        const uint32_t kbase = sb + ((tt & 1) ? SM_K1 : SM_K0);
        const uint32_t vbase = sb + ((tt & 1) ? SM_V1 : SM_V0);

        // ---- prefetch next K/V tile into registers (consumed at loop end) ----
        float4 kf[4], vf[4];
        if (tt < NTILES - 1) {
            const size_t nb = (size_t)(tt + 1) * BN;
            #pragma unroll
            for (int j = 0; j < 4; j++) {
                int row = rbase + 16 * j;
                kf[j] = *(const float4*)(kb + (nb + row) * Dh + cc * 4);
                vf[j] = *(const float4*)(vb + (nb + row) * Dh + cc * 4);
            }
        }

        // ---- S = Q K^T : 4 k-steps, 8 n-tiles ----
        float c[8][4];
        #pragma unroll
        for (int nf = 0; nf < 8; nf++)
            #pragma unroll
            for (int r = 0; r < 4; r++) c[nf][r] = 0.f;

        #pragma unroll
        for (int ks = 0; ks < 4; ks++) {
            uint32_t a[4];
            ldm_x4(a, qaddr + ks * 32);
            #pragma unroll
            for (int p = 0; p < 4; p++) {
                uint32_t b[4];
                ldm_x4(b, kbase + p * (16 * RPITCH) + ks * 32 + krow_off);
                mma16(c[2 * p],     a, b[0], b[1]);
                mma16(c[2 * p + 1], a, b[2], b[3]);
            }
        }

        // ---- poly + relu + rowsum + in-register repack to A-fragments ----
        uint32_t ap[4][4];
        #pragma unroll
        for (int nf = 0; nf < 8; nf++) {
            float p0 = fmaxf(fmaf(fmaf(a2c, c[nf][0], b1c), c[nf][0], g0c), 0.f);
            float p1 = fmaxf(fmaf(fmaf(a2c, c[nf][1], b1c), c[nf][1], g0c), 0.f);
            float p2 = fmaxf(fmaf(fmaf(a2c, c[nf][2], b1c), c[nf][2], g0c), 0.f);
            float p3 = fmaxf(fmaf(fmaf(a2c, c[nf][3], b1c), c[nf][3], g0c), 0.f);
            uint32_t u01 = ph2(p0, p1);
            uint32_t u23 = ph2(p2, p3);
            // rowsum uses the SAME fp16-rounded values the O-GEMM consumes
            __half2 h01 = *(__half2*)&u01, h23 = *(__half2*)&u23;
            float2 f01 = __half22float2(h01), f23 = __half22float2(h23);
            rs0 += f01.x + f01.y;
            rs1 += f23.x + f23.y;
            ap[nf >> 1][(nf & 1) * 2 + 0] = u01;
            ap[nf >> 1][(nf & 1) * 2 + 1] = u23;
        }

        // ---- O += attn @ V : A from registers, B via ldmatrix.trans ----
        #pragma unroll
        for (int ks2 = 0; ks2 < 4; ks2++) {
            #pragma unroll
            for (int p = 0; p < 4; p++) {
                uint32_t b[4];
                ldm_x4t(b, vbase + ks2 * (16 * RPITCH) + p * 32 + vrow_off);
                mma16(o[2 * p],     ap[ks2], b[0], b[1]);
                mma16(o[2 * p + 1], ap[ks2], b[2], b[3]);
            }
        }

        // ---- store prefetched tile into the other buffer ----
        if (tt < NTILES - 1) {
            const uint32_t kdst = sb + ((tt & 1) ? SM_K0 : SM_K1) - sb;
            char* kd = smc + (((tt & 1) ? SM_K0 : SM_K1));
            char* vd = smc + (((tt & 1) ? SM_V0 : SM_V1));
            (void)kdst;
            #pragma unroll
            for (int j = 0; j < 4; j++) {
                int row = rbase + 16 * j;
                *(uint2*)(kd + row * RPITCH + cc * 8) =
                    make_uint2(ph2(kf[j].x, kf[j].y), ph2(kf[j].z, kf[j].w));
                *(uint2*)(vd + row * RPITCH + cc * 8) =
                    make_uint2(ph2(vf[j].x, vf[j].y), ph2(vf[j].z, vf[j].w));
            }
            __syncthreads();
        }
    }

    // ---- rowsum closes within the warp: sum over the 4 t-lanes ----
    rs0 += __shfl_xor_sync(0xFFFFFFFFu, rs0, 1);
    rs0 += __shfl_xor_sync(0xFFFFFFFFu, rs0, 2);
    rs1 += __shfl_xor_sync(0xFFFFFFFFu, rs1, 1);
    rs1 += __shfl_xor_sync(0xFFFFFFFFu, rs1, 2);
    const float inv0 = 1.f / (rs0 + EPS);
    const float inv1 = 1.f / (rs1 + EPS);

    // ---- normalize + store ----
    const int row0 = m0 + w * 16 + g;
    #pragma unroll
    for (int d = 0; d < 8; d++) {
        float2 lo = {o[d][0] * inv0, o[d][1] * inv0};
        float2 hi = {o[d][2] * inv1, o[d][3] * inv1};
        *(float2*)(ob + (size_t)row0 * Dh + d * 8 + 2 * t)       = lo;
        *(float2*)(ob + (size_t)(row0 + 8) * Dh + d * 8 + 2 * t) = hi;
    }
}

extern "C" void kernel_launch(void* const* d_in, const int* in_sizes, int n_in,
                              void* d_out, int out_size)
{
    const float* q     = (const float*)d_in[0];
    const float* k     = (const float*)d_in[1];
    const float* v     = (const float*)d_in[2];
    const float* alpha = (const float*)d_in[3];
    const float* beta  = (const float*)d_in[4];
    const float* gamma = (const float*)d_in[5];
    float* out = (float*)d_out;

    cudaFuncSetAttribute(l2q_h2_kernel,
                         cudaFuncAttributeMaxDynamicSharedMemorySize, SMEM_BYTES);

    dim3 grid(Nq / BM, Bsz * H);
    l2q_h2_kernel<<<grid, NT, SMEM_BYTES>>>(q, k, v, alpha, beta, gamma, out);
}